// round 1
// baseline (speedup 1.0000x reference)
#include <cuda_runtime.h>

#define BB 32
#define SS 4096
#define CC 768
#define HH 12
#define DD 64
#define NSPLIT 16
#define SCHUNK (SS / NSPLIT)   // 256

// ---- scratch (device globals: no allocation allowed) ----
__device__ float g_qh[HH * DD];                                   // scaled probe query
__device__ float g_wk[HH * CC];                                   // folded key weights
__device__ float g_sbias[HH];                                     // qh . bk
__device__ float g_scores[(size_t)BB * HH * SS];                  // scores -> attn (in place)
__device__ float g_ypart[(size_t)NSPLIT * BB * HH * CC];          // split-S partial y
__device__ float g_ctx[BB * HH * DD];                             // context vectors

typedef unsigned long long u64;

__device__ __forceinline__ u64 pk2(float a, float b) {
    u64 r; asm("mov.b64 %0,{%1,%2};" : "=l"(r) : "f"(a), "f"(b)); return r;
}
__device__ __forceinline__ float2 up2(u64 v) {
    float2 r; asm("mov.b64 {%0,%1},%2;" : "=f"(r.x), "=f"(r.y) : "l"(v)); return r;
}
__device__ __forceinline__ void ffma2(u64& d, u64 a, u64 b) {
    asm("fma.rn.f32x2 %0,%1,%2,%0;" : "+l"(d) : "l"(a), "l"(b));
}
__device__ __forceinline__ u64 vadd2(u64 a, u64 b) {
    u64 r; asm("add.rn.f32x2 %0,%1,%2;" : "=l"(r) : "l"(a), "l"(b)); return r;
}

// ---- prep 1: qh[h,d] = (probe @ Wq + bq) * 1/sqrt(D) ----
__global__ void k_prep_qh(const float* __restrict__ probe,
                          const float* __restrict__ Wq,
                          const float* __restrict__ bq) {
    int h = blockIdx.x, t = threadIdx.x;
    int d = t & 63, part = t >> 6;                // 4 partial sums per d
    float acc = 0.f;
    for (int c = part; c < CC; c += 4)
        acc = fmaf(probe[c], Wq[(size_t)c * CC + h * DD + d], acc);
    __shared__ float red[4][64];
    red[part][d] = acc;
    __syncthreads();
    if (t < 64) {
        float v = red[0][t] + red[1][t] + red[2][t] + red[3][t];
        g_qh[h * DD + t] = (v + bq[h * DD + t]) * 0.125f;   // 1/sqrt(64)
    }
}

// ---- prep 2: wk[h,c] = sum_d Wk[c,h,d]*qh[h,d];  sbias[h] = qh[h,:].bk[h,:] ----
__global__ void k_prep_wk(const float* __restrict__ Wk,
                          const float* __restrict__ bk) {
    int h = blockIdx.x, t = threadIdx.x;
    __shared__ float qs[DD];
    if (t < DD) qs[t] = g_qh[h * DD + t];
    __syncthreads();
    for (int c = t; c < CC; c += 256) {
        const float4* w = (const float4*)(Wk + (size_t)c * CC + h * DD);
        float a = 0.f;
        #pragma unroll
        for (int j = 0; j < DD / 4; j++) {
            float4 wv = w[j];
            const float4 qv = *(const float4*)(qs + j * 4);
            a += wv.x * qv.x + wv.y * qv.y + wv.z * qv.z + wv.w * qv.w;
        }
        g_wk[h * CC + c] = a;
    }
    if (t == 0) {
        float a = 0.f;
        for (int d2 = 0; d2 < DD; d2++) a += bk[h * DD + d2] * qs[d2];
        g_sbias[h] = a;
    }
}

// ---- pass 1: scores[b,h,s] = x[b,s,:] . wk[h,:] + sbias[h] ----
// Warp layout: 4 rows x 8 lanes/row. Each LDG.128 covers 4 full 128B lines.
__global__ __launch_bounds__(256) void k_scores(const float* __restrict__ x) {
    __shared__ float wks[HH * CC];   // 36 KB
    __shared__ float sbs[HH];
    int t = threadIdx.x;
    for (int i = t; i < HH * CC; i += 256) wks[i] = g_wk[i];
    if (t < HH) sbs[t] = g_sbias[t];
    __syncthreads();

    int b = blockIdx.y;
    int lane = t & 31, w = t >> 5;
    int g = lane >> 3, q = lane & 7;
    const float* xb = x + (size_t)b * SS * CC;

    for (int pass = 0; pass < 4; pass++) {
        int row = blockIdx.x * 128 + pass * 32 + w * 4 + g;
        const float4* xr = (const float4*)(xb + (size_t)row * CC);
        u64 acc[HH];
        #pragma unroll
        for (int h = 0; h < HH; h++) acc[h] = 0ull;

        #pragma unroll 4
        for (int j = 0; j < 24; j++) {
            int c4 = j * 8 + q;                    // float4 index within row
            float4 xv = xr[c4];
            u64 xlo = pk2(xv.x, xv.y), xhi = pk2(xv.z, xv.w);
            #pragma unroll
            for (int h = 0; h < HH; h++) {
                float4 wv = *(const float4*)(wks + h * CC + c4 * 4);
                ffma2(acc[h], xlo, pk2(wv.x, wv.y));
                ffma2(acc[h], xhi, pk2(wv.z, wv.w));
            }
        }
        // reduce across the 8 lanes of this row (xor over bits 0..2)
        #pragma unroll
        for (int h = 0; h < HH; h++) {
            u64 v = acc[h];
            v = vadd2(v, __shfl_xor_sync(0xffffffffu, v, 4));
            v = vadd2(v, __shfl_xor_sync(0xffffffffu, v, 2));
            v = vadd2(v, __shfl_xor_sync(0xffffffffu, v, 1));
            acc[h] = v;
        }
        if (q == 0) {
            #pragma unroll
            for (int h = 0; h < HH; h++) {
                float2 f = up2(acc[h]);
                g_scores[((size_t)b * HH + h) * SS + row] = f.x + f.y + sbs[h];
            }
        }
    }
}

// ---- softmax over S per (b,h), in place ----
__global__ __launch_bounds__(256) void k_softmax() {
    int t = threadIdx.x;
    float4* sc4 = (float4*)(g_scores + (size_t)blockIdx.x * SS);
    float4 v[4];
    float m = -1e30f;
    #pragma unroll
    for (int i = 0; i < 4; i++) {
        v[i] = sc4[t + i * 256];
        m = fmaxf(m, fmaxf(fmaxf(v[i].x, v[i].y), fmaxf(v[i].z, v[i].w)));
    }
    __shared__ float red[32];
    #pragma unroll
    for (int o = 16; o; o >>= 1) m = fmaxf(m, __shfl_xor_sync(~0u, m, o));
    if ((t & 31) == 0) red[t >> 5] = m;
    __syncthreads();
    if (t < 32) {
        float mm = (t < 8) ? red[t] : -1e30f;
        #pragma unroll
        for (int o = 4; o; o >>= 1) mm = fmaxf(mm, __shfl_xor_sync(~0u, mm, o));
        red[t] = mm;
    }
    __syncthreads();
    m = red[0];
    __syncthreads();   // protect red before reuse

    float s = 0.f;
    #pragma unroll
    for (int i = 0; i < 4; i++) {
        v[i].x = __expf(v[i].x - m); v[i].y = __expf(v[i].y - m);
        v[i].z = __expf(v[i].z - m); v[i].w = __expf(v[i].w - m);
        s += (v[i].x + v[i].y) + (v[i].z + v[i].w);
    }
    #pragma unroll
    for (int o = 16; o; o >>= 1) s += __shfl_xor_sync(~0u, s, o);
    if ((t & 31) == 0) red[t >> 5] = s;
    __syncthreads();
    if (t < 32) {
        float ss2 = (t < 8) ? red[t] : 0.f;
        #pragma unroll
        for (int o = 4; o; o >>= 1) ss2 += __shfl_xor_sync(~0u, ss2, o);
        red[t] = ss2;
    }
    __syncthreads();
    float inv = 1.f / red[0];
    #pragma unroll
    for (int i = 0; i < 4; i++) {
        v[i].x *= inv; v[i].y *= inv; v[i].z *= inv; v[i].w *= inv;
        sc4[t + i * 256] = v[i];
    }
}

// ---- pass 2: y_part[sp,b,h,:] = sum_{s in chunk} attn[b,h,s] * x[b,s,:] ----
// Thread t owns columns [4t, 4t+4): perfectly coalesced x reads.
__global__ __launch_bounds__(192) void k_accum(const float* __restrict__ x) {
    int b = blockIdx.y, sp = blockIdx.x, t = threadIdx.x;
    __shared__ u64 at2[HH][64];                    // attn duplicated as f32x2
    const float* xb = x + (size_t)b * SS * CC + t * 4;
    int s0 = sp * SCHUNK;

    u64 acc[HH][2];
    #pragma unroll
    for (int h = 0; h < HH; h++) { acc[h][0] = 0ull; acc[h][1] = 0ull; }

    for (int tile = 0; tile < SCHUNK / 64; tile++) {
        int sb = s0 + tile * 64;
        __syncthreads();
        for (int i = t; i < HH * 64; i += 192) {
            int h = i >> 6, ss = i & 63;
            float p = g_scores[((size_t)b * HH + h) * SS + sb + ss];
            at2[h][ss] = pk2(p, p);
        }
        __syncthreads();
        for (int ss = 0; ss < 64; ss++) {
            float4 xv = *(const float4*)(xb + (size_t)(sb + ss) * CC);
            u64 xlo = pk2(xv.x, xv.y), xhi = pk2(xv.z, xv.w);
            #pragma unroll
            for (int h = 0; h < HH; h++) {
                u64 p = at2[h][ss];
                ffma2(acc[h][0], p, xlo);
                ffma2(acc[h][1], p, xhi);
            }
        }
    }
    float* yp = g_ypart + ((size_t)sp * BB + b) * (HH * CC) + t * 4;
    #pragma unroll
    for (int h = 0; h < HH; h++) {
        float2 lo = up2(acc[h][0]), hi = up2(acc[h][1]);
        *(float4*)(yp + h * CC) = make_float4(lo.x, lo.y, hi.x, hi.y);
    }
}

// ---- epilogue A: reduce splits, ctx[b,o] = sum_c y[b,h,c]*Wv[c,o] + bv[o] ----
__global__ __launch_bounds__(192) void k_ctx(const float* __restrict__ Wv,
                                             const float* __restrict__ bv) {
    int b = blockIdx.y, part = blockIdx.x, t = threadIdx.x;   // part: 0..3
    int o0 = part * 192;
    int h0 = o0 / DD;                                          // 3 heads per part
    __shared__ float ys[3 * CC];                               // 9 KB
    for (int i = t; i < 3 * CC; i += 192) {
        size_t base = (size_t)b * HH * CC + (size_t)h0 * CC + i;
        float a = 0.f;
        #pragma unroll
        for (int sp = 0; sp < NSPLIT; sp++)
            a += g_ypart[(size_t)sp * BB * HH * CC + base];
        ys[i] = a;
    }
    __syncthreads();
    int o = o0 + t;
    const float* yrow = ys + (t / DD) * CC;
    float a = bv[o];
    #pragma unroll 8
    for (int c = 0; c < CC; c++)
        a = fmaf(yrow[c], Wv[(size_t)c * CC + o], a);
    g_ctx[b * HH * DD + o] = a;
}

// ---- epilogue B: out[b,c'] = sum_o ctx[b,o]*Wo[o,c'] + bo[c'] ----
__global__ __launch_bounds__(192) void k_out(const float* __restrict__ Wo,
                                             const float* __restrict__ bo,
                                             float* __restrict__ out) {
    int b = blockIdx.y, part = blockIdx.x, t = threadIdx.x;
    __shared__ float cs[HH * DD];
    for (int i = t; i < HH * DD; i += 192) cs[i] = g_ctx[b * HH * DD + i];
    __syncthreads();
    int cp = part * 192 + t;
    float a = bo[cp];
    #pragma unroll 8
    for (int o = 0; o < HH * DD; o++)
        a = fmaf(cs[o], Wo[(size_t)o * CC + cp], a);
    out[(size_t)b * CC + cp] = a;
}

extern "C" void kernel_launch(void* const* d_in, const int* in_sizes, int n_in,
                              void* d_out, int out_size) {
    const float* x     = (const float*)d_in[0];
    const float* probe = (const float*)d_in[1];
    const float* Wq    = (const float*)d_in[2];
    const float* bq    = (const float*)d_in[3];
    const float* Wk    = (const float*)d_in[4];
    const float* bk    = (const float*)d_in[5];
    const float* Wv    = (const float*)d_in[6];
    const float* bv    = (const float*)d_in[7];
    const float* Wo    = (const float*)d_in[8];
    const float* bo    = (const float*)d_in[9];
    float* out = (float*)d_out;

    k_prep_qh<<<HH, 256>>>(probe, Wq, bq);
    k_prep_wk<<<HH, 256>>>(Wk, bk);
    k_scores<<<dim3(SS / 128, BB), 256>>>(x);
    k_softmax<<<BB * HH, 256>>>();
    k_accum<<<dim3(NSPLIT, BB), 192>>>(x);
    k_ctx<<<dim3(4, BB), 192>>>(Wv, bv);
    k_out<<<dim3(4, BB), 192>>>(Wo, bo, out);
}